// round 9
// baseline (speedup 1.0000x reference)
#include <cuda_runtime.h>
#include <cuda_bf16.h>

// Per-block partial sums + completion ticket. g_count is reset to 0 by the
// last block each launch, so every graph replay starts from identical state.
#define MAX_BLOCKS 4096
__device__ double g_partials[MAX_BLOCKS];
__device__ unsigned int g_count;

__device__ __forceinline__ float kl_elem(float mp, float lsp, float mq, float lsq) {
    // elem = (lsq - lsp) + exp(lsp - lsq) + (mq-mp)^2 * exp(-lsq)
    float t = lsp - lsq;
    float dz = mq - mp;
    return -t + __expf(t) + dz * dz * __expf(-lsq);
}

#define THREADS 512
#define WARPS (THREADS / 32)

__global__ void __launch_bounds__(THREADS, 4)
kl_fused_kernel(const float4* __restrict__ mp,
                const float4* __restrict__ lsp,
                const float4* __restrict__ mq,
                const float4* __restrict__ lsq,
                int n4,
                float* __restrict__ out,
                double inv_nsamples, double d_chan) {
    float sum = 0.0f;
    int idx = blockIdx.x * blockDim.x + threadIdx.x;
    int stride = gridDim.x * blockDim.x;

    // Proven streaming loop: 4 independent LDG.E.128 per iteration, 32 regs,
    // grid-stride interleave (uniform channel spread via addr hash).
    for (int i = idx; i < n4; i += stride) {
        float4 a = __ldcs(&mp[i]);
        float4 p = __ldcs(&lsp[i]);
        float4 b = __ldcs(&mq[i]);
        float4 q = __ldcs(&lsq[i]);
        sum += kl_elem(a.x, p.x, b.x, q.x);
        sum += kl_elem(a.y, p.y, b.y, q.y);
        sum += kl_elem(a.z, p.z, b.z, q.z);
        sum += kl_elem(a.w, p.w, b.w, q.w);
    }

    // Warp reduction (fp32)
    #pragma unroll
    for (int o = 16; o > 0; o >>= 1)
        sum += __shfl_xor_sync(0xFFFFFFFFu, sum, o);

    // Block reduction via shared memory (16 warps)
    __shared__ float wsums[WARPS];
    __shared__ bool is_last;
    int wid = threadIdx.x >> 5;
    int lid = threadIdx.x & 31;
    if (lid == 0) wsums[wid] = sum;
    __syncthreads();

    // ONE thread per block: write partial, fence, take ticket.
    // (gpu-scope fence must stay single-threaded: block-wide cost 21us in R7.)
    if (threadIdx.x == 0) {
        float v = 0.0f;
        #pragma unroll
        for (int w = 0; w < WARPS; w++) v += wsums[w];
        g_partials[blockIdx.x] = (double)v;
        __threadfence();
        unsigned int ticket = atomicAdd(&g_count, 1u);
        is_last = (ticket == gridDim.x - 1);
    }
    __syncthreads();

    // Last block: reduce all partials, write output, reset ticket.
    if (is_last) {
        double acc = 0.0;
        for (int b = threadIdx.x; b < gridDim.x; b += blockDim.x)
            acc += g_partials[b];
        #pragma unroll
        for (int o = 16; o > 0; o >>= 1)
            acc += __shfl_xor_sync(0xFFFFFFFFu, acc, o);
        __shared__ double dsums[WARPS];
        if (lid == 0) dsums[wid] = acc;
        __syncthreads();
        if (threadIdx.x == 0) {
            double t = 0.0;
            #pragma unroll
            for (int w = 0; w < WARPS; w++) t += dsums[w];
            out[0] = (float)(0.5 * (t * inv_nsamples - d_chan));
            g_count = 0;  // deterministic state for next graph replay
        }
    }
}

extern "C" void kernel_launch(void* const* d_in, const int* in_sizes, int n_in,
                              void* d_out, int out_size) {
    const float4* mp  = (const float4*)d_in[0];
    const float4* lsp = (const float4*)d_in[1];
    const float4* mq  = (const float4*)d_in[2];
    const float4* lsq = (const float4*)d_in[3];
    float* out = (float*)d_out;

    const int n = in_sizes[0];          // 29,491,200 elements
    const int n4 = n / 4;               // 7,372,800 float4s
    const int d_chan = 3;               // channel dim (shape[1])
    const long long n_samples = (long long)n / d_chan;

    const int blocks = 148 * 8;         // 1184: 2 waves at occ 4 (512 thr/CTA)

    kl_fused_kernel<<<blocks, THREADS>>>(mp, lsp, mq, lsq, n4, out,
                                         1.0 / (double)n_samples, (double)d_chan);
}

// round 10
// speedup vs baseline: 1.0603x; 1.0603x over previous
#include <cuda_runtime.h>
#include <cuda_bf16.h>

// Global scalar accumulator (device global: no allocations allowed).
__device__ double g_accum;

__global__ void kl_init_kernel() {
    g_accum = 0.0;
}

__device__ __forceinline__ float kl_elem(float mp, float lsp, float mq, float lsq) {
    // elem = (lsq - lsp) + exp(lsp - lsq) + (mq-mp)^2 * exp(-lsq)
    float t = lsp - lsq;
    float dz = mq - mp;
    return -t + __expf(t) + dz * dz * __expf(-lsq);
}

__global__ void __launch_bounds__(256, 8)
kl_reduce_kernel(const float4* __restrict__ mp,
                 const float4* __restrict__ lsp,
                 const float4* __restrict__ mq,
                 const float4* __restrict__ lsq,
                 int n4) {
    float sum = 0.0f;
    int idx = blockIdx.x * blockDim.x + threadIdx.x;
    int stride = gridDim.x * blockDim.x;

    // Best-measured streaming loop: 4 independent LDG.E.128 per iteration,
    // 32 regs, grid-stride interleave (uniform HBM channel spread).
    for (int i = idx; i < n4; i += stride) {
        float4 a = __ldcs(&mp[i]);
        float4 p = __ldcs(&lsp[i]);
        float4 b = __ldcs(&mq[i]);
        float4 q = __ldcs(&lsq[i]);
        sum += kl_elem(a.x, p.x, b.x, q.x);
        sum += kl_elem(a.y, p.y, b.y, q.y);
        sum += kl_elem(a.z, p.z, b.z, q.z);
        sum += kl_elem(a.w, p.w, b.w, q.w);
    }

    // Warp reduction
    #pragma unroll
    for (int o = 16; o > 0; o >>= 1)
        sum += __shfl_xor_sync(0xFFFFFFFFu, sum, o);

    // Block reduction via shared memory (8 warps)
    __shared__ float wsums[8];
    int wid = threadIdx.x >> 5;
    int lid = threadIdx.x & 31;
    if (lid == 0) wsums[wid] = sum;
    __syncthreads();

    if (wid == 0) {
        float v = (lid < (blockDim.x >> 5)) ? wsums[lid] : 0.0f;
        #pragma unroll
        for (int o = 4; o > 0; o >>= 1)
            v += __shfl_xor_sync(0xFFFFFFFFu, v, o);
        if (lid == 0)
            atomicAdd(&g_accum, (double)v);
    }
}

__global__ void kl_finalize_kernel(float* out, double inv_nsamples, double d) {
    out[0] = (float)(0.5 * (g_accum * inv_nsamples - d));
}

extern "C" void kernel_launch(void* const* d_in, const int* in_sizes, int n_in,
                              void* d_out, int out_size) {
    const float4* mp  = (const float4*)d_in[0];
    const float4* lsp = (const float4*)d_in[1];
    const float4* mq  = (const float4*)d_in[2];
    const float4* lsq = (const float4*)d_in[3];
    float* out = (float*)d_out;

    const int n = in_sizes[0];          // 29,491,200 elements (b=2, d=3, 160*192*160)
    const int n4 = n / 4;               // float4 count (n divisible by 4)
    const int d_chan = 3;               // channel dim (shape[1])
    const long long n_samples = (long long)n / d_chan;  // b*D*H*W

    const int threads = 256;
    const int blocks = 148 * 16;        // 2368 blocks, grid-stride

    kl_init_kernel<<<1, 1>>>();
    kl_reduce_kernel<<<blocks, threads>>>(mp, lsp, mq, lsq, n4);
    kl_finalize_kernel<<<1, 1>>>(out, 1.0 / (double)n_samples, (double)d_chan);
}

// round 11
// speedup vs baseline: 1.0878x; 1.0259x over previous
#include <cuda_runtime.h>
#include <cuda_bf16.h>

// Global scalar accumulator. Zero at module load for the correctness run;
// kl_finalize_kernel resets it to 0.0 after consuming it, so every graph
// replay starts from identical state (self-restoring, deterministic).
__device__ double g_accum;

__device__ __forceinline__ float kl_elem(float mp, float lsp, float mq, float lsq) {
    // elem = (lsq - lsp) + exp(lsp - lsq) + (mq-mp)^2 * exp(-lsq)
    float t = lsp - lsq;
    float dz = mq - mp;
    return -t + __expf(t) + dz * dz * __expf(-lsq);
}

__global__ void __launch_bounds__(256, 8)
kl_reduce_kernel(const float4* __restrict__ mp,
                 const float4* __restrict__ lsp,
                 const float4* __restrict__ mq,
                 const float4* __restrict__ lsq,
                 int n4) {
    float sum = 0.0f;
    int idx = blockIdx.x * blockDim.x + threadIdx.x;
    int stride = gridDim.x * blockDim.x;

    // Best-measured streaming loop (unchanged since R2): 4 independent
    // LDG.E.128 per iteration, 32 regs, grid-stride interleave.
    for (int i = idx; i < n4; i += stride) {
        float4 a = __ldcs(&mp[i]);
        float4 p = __ldcs(&lsp[i]);
        float4 b = __ldcs(&mq[i]);
        float4 q = __ldcs(&lsq[i]);
        sum += kl_elem(a.x, p.x, b.x, q.x);
        sum += kl_elem(a.y, p.y, b.y, q.y);
        sum += kl_elem(a.z, p.z, b.z, q.z);
        sum += kl_elem(a.w, p.w, b.w, q.w);
    }

    // Warp reduction
    #pragma unroll
    for (int o = 16; o > 0; o >>= 1)
        sum += __shfl_xor_sync(0xFFFFFFFFu, sum, o);

    // Block reduction via shared memory (8 warps)
    __shared__ float wsums[8];
    int wid = threadIdx.x >> 5;
    int lid = threadIdx.x & 31;
    if (lid == 0) wsums[wid] = sum;
    __syncthreads();

    if (wid == 0) {
        float v = (lid < (blockDim.x >> 5)) ? wsums[lid] : 0.0f;
        #pragma unroll
        for (int o = 4; o > 0; o >>= 1)
            v += __shfl_xor_sync(0xFFFFFFFFu, v, o);
        if (lid == 0)
            atomicAdd(&g_accum, (double)v);
    }
}

__global__ void kl_finalize_kernel(float* out, double inv_nsamples, double d) {
    out[0] = (float)(0.5 * (g_accum * inv_nsamples - d));
    g_accum = 0.0;   // restore state for the next graph replay
}

extern "C" void kernel_launch(void* const* d_in, const int* in_sizes, int n_in,
                              void* d_out, int out_size) {
    const float4* mp  = (const float4*)d_in[0];
    const float4* lsp = (const float4*)d_in[1];
    const float4* mq  = (const float4*)d_in[2];
    const float4* lsq = (const float4*)d_in[3];
    float* out = (float*)d_out;

    const int n = in_sizes[0];          // 29,491,200 elements (b=2, d=3, 160*192*160)
    const int n4 = n / 4;               // float4 count (n divisible by 4)
    const int d_chan = 3;               // channel dim (shape[1])
    const long long n_samples = (long long)n / d_chan;  // b*D*H*W

    const int threads = 256;
    const int blocks = 148 * 16;        // 2368 blocks, grid-stride

    kl_reduce_kernel<<<blocks, threads>>>(mp, lsp, mq, lsq, n4);
    kl_finalize_kernel<<<1, 1>>>(out, 1.0 / (double)n_samples, (double)d_chan);
}